// round 1
// baseline (speedup 1.0000x reference)
#include <cuda_runtime.h>
#include <math.h>

#define NNODE 100000
#define NEDGE 200000
#define NGRAPH 4096
#define D 300
#define NLAYER 5
#define HDIM 600
#define DECH 1200
#define MAXO 1783
#define D4 (D/4)

// ---------------- scratch arena (no cudaMalloc allowed) ----------------
// offsets in floats
#define OFF_H     0ull            // 100000*300 = 30,000,000
#define OFF_Z     30000000ull     // 30,000,000
#define OFF_Z1    60000000ull     // 100000*600 = 60,000,000
#define OFF_Z2    120000000ull    // 30,000,000
#define OFF_HG    150000000ull    // 4096*300 = 1,228,800
#define OFF_MU    151228800ull    // 1,228,800
#define OFF_ZDEC  152457600ull    // 4096*1200 = 4,915,200
#define OFF_STATS 157372800ull    // 2*1216 = 2,432
#define OFF_BNA   157375232ull    // 1,216
#define OFF_BNB   157376448ull    // 1,216
#define SCRATCH_FLOATS 157377664ull

__device__ float g_scratch[SCRATCH_FLOATS];

// ---------------- small elementwise kernels ----------------

__global__ void k_gather(const float* __restrict__ atom_emb,
                         const int* __restrict__ x_idx,
                         float* __restrict__ h) {
    int t = blockIdx.x * blockDim.x + threadIdx.x;
    if (t >= NNODE * D4) return;
    int i = t / D4;
    int c = (t - i * D4) * 4;
    int a = x_idx[i];
    float4 v = *reinterpret_cast<const float4*>(atom_emb + (size_t)a * D + c);
    *reinterpret_cast<float4*>(h + (size_t)i * D + c) = v;
}

__global__ void k_scale(const float* __restrict__ h,
                        const float* __restrict__ eps, int l,
                        float* __restrict__ z) {
    int t = blockIdx.x * blockDim.x + threadIdx.x;
    if (t >= NNODE * D4) return;
    float s = 1.0f + eps[l];
    float4 v = *reinterpret_cast<const float4*>(h + (size_t)t * 4);
    v.x *= s; v.y *= s; v.z *= s; v.w *= s;
    *reinterpret_cast<float4*>(z + (size_t)t * 4) = v;
}

__global__ void k_edge(const float* __restrict__ h,
                       const float* __restrict__ emb,   // edge_emb for layer l: [5, D]
                       const int* __restrict__ attr,
                       const int* __restrict__ eidx,
                       float* __restrict__ z) {
    int t = blockIdx.x * blockDim.x + threadIdx.x;
    if (t >= NEDGE * D4) return;
    int e = t / D4;
    int c = (t - e * D4) * 4;
    int src = eidx[e];
    int dst = eidx[NEDGE + e];
    int a = attr[e];
    float4 hv = *reinterpret_cast<const float4*>(h + (size_t)src * D + c);
    float4 ev = *reinterpret_cast<const float4*>(emb + (size_t)a * D + c);
    float m0 = fmaxf(hv.x + ev.x, 0.0f);
    float m1 = fmaxf(hv.y + ev.y, 0.0f);
    float m2 = fmaxf(hv.z + ev.z, 0.0f);
    float m3 = fmaxf(hv.w + ev.w, 0.0f);
    float* zp = z + (size_t)dst * D + c;
    atomicAdd(zp + 0, m0);
    atomicAdd(zp + 1, m1);
    atomicAdd(zp + 2, m2);
    atomicAdd(zp + 3, m3);
}

__global__ void k_zero(float* __restrict__ p, int n) {
    int t = blockIdx.x * blockDim.x + threadIdx.x;
    if (t < n) p[t] = 0.0f;
}

#define RED_ROWS 2048
__global__ void k_colreduce(const float* __restrict__ X, int M, int Nc,
                            float* __restrict__ stats) {
    int c = blockIdx.x * blockDim.x + threadIdx.x;
    if (c >= Nc) return;
    int r0 = blockIdx.y * RED_ROWS;
    int r1 = r0 + RED_ROWS; if (r1 > M) r1 = M;
    float s = 0.0f, s2 = 0.0f;
    for (int r = r0; r < r1; r++) {
        float v = X[(size_t)r * Nc + c];
        s += v;
        s2 += v * v;
    }
    atomicAdd(&stats[c], s);
    atomicAdd(&stats[Nc + c], s2);
}

__global__ void k_bnparam(const float* __restrict__ stats,
                          const float* __restrict__ g,
                          const float* __restrict__ b,
                          int Nc, float invM,
                          float* __restrict__ bnA, float* __restrict__ bnB) {
    int c = blockIdx.x * blockDim.x + threadIdx.x;
    if (c >= Nc) return;
    float mean = stats[c] * invM;
    float var = stats[Nc + c] * invM - mean * mean;
    float a = g[c] * rsqrtf(var + 1e-5f);
    bnA[c] = a;
    bnB[c] = b[c] - mean * a;
}

__global__ void k_finalize(const float* __restrict__ z2,
                           const float* __restrict__ bnA,
                           const float* __restrict__ bnB,
                           int dorelu, float* __restrict__ h) {
    int t = blockIdx.x * blockDim.x + threadIdx.x;
    if (t >= NNODE * D4) return;
    size_t base = (size_t)t * 4;
    int c = (int)(base % D);
    float4 zv = *reinterpret_cast<const float4*>(z2 + base);
    float4 hv = *reinterpret_cast<const float4*>(h + base);
    float v0 = bnA[c + 0] * zv.x + bnB[c + 0];
    float v1 = bnA[c + 1] * zv.y + bnB[c + 1];
    float v2 = bnA[c + 2] * zv.z + bnB[c + 2];
    float v3 = bnA[c + 3] * zv.w + bnB[c + 3];
    if (dorelu) {
        v0 = fmaxf(v0, 0.0f); v1 = fmaxf(v1, 0.0f);
        v2 = fmaxf(v2, 0.0f); v3 = fmaxf(v3, 0.0f);
    }
    hv.x += v0; hv.y += v1; hv.z += v2; hv.w += v3;
    *reinterpret_cast<float4*>(h + base) = hv;
}

__global__ void k_hginit(float* __restrict__ hg) {
    int t = blockIdx.x * blockDim.x + threadIdx.x;
    if (t < NGRAPH * D) hg[t] = -INFINITY;
}

__device__ __forceinline__ void atomicMaxF(float* addr, float v) {
    if (v >= 0.0f) atomicMax((int*)addr, __float_as_int(v));
    else atomicMin((unsigned int*)addr, __float_as_uint(v));
}

__global__ void k_segmax(const float* __restrict__ h,
                         const int* __restrict__ batch,
                         float* __restrict__ hg) {
    int t = blockIdx.x * blockDim.x + threadIdx.x;
    if (t >= NNODE * D4) return;
    int i = t / D4;
    int c = (t - i * D4) * 4;
    int g = batch[i];
    float4 v = *reinterpret_cast<const float4*>(h + (size_t)i * D + c);
    float* p = hg + (size_t)g * D + c;
    atomicMaxF(p + 0, v.x);
    atomicMaxF(p + 1, v.y);
    atomicMaxF(p + 2, v.z);
    atomicMaxF(p + 3, v.w);
}

// ---------------- GEMM: 128x128x8 tiles, 256 threads, 8x8 per thread ----------------
// MODE 0: C = A@B + bias
// MODE 1: C = relu(bnA*A + bnB) @ B + bias          (A preproc per k-column)
// MODE 2: C = silu(A)@B + bias; cols <D -> C (mu) and C3; cols >=D -> softplus+1e-7 -> C2
// MODE 3: C = gelu(bnA*A + bnB) @ B + bias; store only col<N with row stride ldc

#define MODE_PLAIN 0
#define MODE_BNRELU 1
#define MODE_DIST 2
#define MODE_DEC 3

#define BM 128
#define BN 128
#define BK 8

template <int MODE>
__global__ void __launch_bounds__(256, 2)
k_gemm(const float* __restrict__ A, const float* __restrict__ B,
       const float* __restrict__ bias,
       float* __restrict__ C, float* __restrict__ C2, float* __restrict__ C3,
       int M, int N, int K, int ldb, int NB, int ldc,
       const float* __restrict__ bnA, const float* __restrict__ bnB) {
    __shared__ float As[BK][BM];
    __shared__ float Bs[BK][BN];
    int tid = threadIdx.x;
    int row0 = blockIdx.y * BM;
    int col0 = blockIdx.x * BN;
    int tx = tid & 15, ty = tid >> 4;

    int arow = tid >> 1;
    int ak = (tid & 1) << 2;
    int bkr = tid >> 5;
    int bc = (tid & 31) << 2;

    float acc[8][8];
#pragma unroll
    for (int i = 0; i < 8; i++)
#pragma unroll
        for (int j = 0; j < 8; j++) acc[i][j] = 0.0f;

    for (int kb = 0; kb < K; kb += BK) {
        // load + preprocess A tile (K%4==0 in all uses, so float4 groups are all-valid or all-invalid)
        float4 av = make_float4(0.f, 0.f, 0.f, 0.f);
        int gr = row0 + arow;
        int gk = kb + ak;
        if (gr < M && gk < K) {
            av = *reinterpret_cast<const float4*>(A + (size_t)gr * K + gk);
            if (MODE == MODE_BNRELU) {
                av.x = fmaxf(fmaf(bnA[gk + 0], av.x, bnB[gk + 0]), 0.0f);
                av.y = fmaxf(fmaf(bnA[gk + 1], av.y, bnB[gk + 1]), 0.0f);
                av.z = fmaxf(fmaf(bnA[gk + 2], av.z, bnB[gk + 2]), 0.0f);
                av.w = fmaxf(fmaf(bnA[gk + 3], av.w, bnB[gk + 3]), 0.0f);
            } else if (MODE == MODE_DIST) {
                av.x = av.x / (1.0f + expf(-av.x));
                av.y = av.y / (1.0f + expf(-av.y));
                av.z = av.z / (1.0f + expf(-av.z));
                av.w = av.w / (1.0f + expf(-av.w));
            } else if (MODE == MODE_DEC) {
                float t0 = fmaf(bnA[gk + 0], av.x, bnB[gk + 0]);
                float t1 = fmaf(bnA[gk + 1], av.y, bnB[gk + 1]);
                float t2 = fmaf(bnA[gk + 2], av.z, bnB[gk + 2]);
                float t3 = fmaf(bnA[gk + 3], av.w, bnB[gk + 3]);
                av.x = 0.5f * t0 * (1.0f + erff(t0 * 0.70710678118654752f));
                av.y = 0.5f * t1 * (1.0f + erff(t1 * 0.70710678118654752f));
                av.z = 0.5f * t2 * (1.0f + erff(t2 * 0.70710678118654752f));
                av.w = 0.5f * t3 * (1.0f + erff(t3 * 0.70710678118654752f));
            }
        }
        As[ak + 0][arow] = av.x;
        As[ak + 1][arow] = av.y;
        As[ak + 2][arow] = av.z;
        As[ak + 3][arow] = av.w;

        // load B tile (scalar loads: ldb may be odd, e.g. 1783)
        int gkb = kb + bkr;
#pragma unroll
        for (int j = 0; j < 4; j++) {
            int n = col0 + bc + j;
            Bs[bkr][bc + j] = (gkb < K && n < NB)
                ? B[(size_t)gkb * ldb + n] : 0.0f;
        }
        __syncthreads();

#pragma unroll
        for (int kk = 0; kk < BK; kk++) {
            float a[8], b[8];
#pragma unroll
            for (int i = 0; i < 8; i++) a[i] = As[kk][ty * 8 + i];
#pragma unroll
            for (int j = 0; j < 8; j++) b[j] = Bs[kk][tx * 8 + j];
#pragma unroll
            for (int i = 0; i < 8; i++)
#pragma unroll
                for (int j = 0; j < 8; j++)
                    acc[i][j] = fmaf(a[i], b[j], acc[i][j]);
        }
        __syncthreads();
    }

    // epilogue
#pragma unroll
    for (int i = 0; i < 8; i++) {
        int r = row0 + ty * 8 + i;
        if (r >= M) continue;
#pragma unroll
        for (int j = 0; j < 8; j++) {
            int c = col0 + tx * 8 + j;
            if (c >= N) continue;
            float v = acc[i][j] + bias[c];
            if (MODE == MODE_DIST) {
                if (c < D) {
                    C[(size_t)r * ldc + c] = v;
                    C3[(size_t)r * D + c] = v;
                } else {
                    float sp = fmaxf(v, 0.0f) + log1pf(expf(-fabsf(v))) + 1e-7f;
                    C2[(size_t)r * ldc + (c - D)] = sp;
                }
            } else {
                C[(size_t)r * ldc + c] = v;
            }
        }
    }
}

// ---------------- host side ----------------

extern "C" void kernel_launch(void* const* d_in, const int* in_sizes, int n_in,
                              void* d_out, int out_size) {
    const float* atom_emb = (const float*)d_in[0];
    const float* edge_emb = (const float*)d_in[1];
    const float* eps      = (const float*)d_in[2];
    const float* conv_w1  = (const float*)d_in[3];
    const float* conv_b1  = (const float*)d_in[4];
    const float* bn1g     = (const float*)d_in[5];
    const float* bn1b     = (const float*)d_in[6];
    const float* conv_w2  = (const float*)d_in[7];
    const float* conv_b2  = (const float*)d_in[8];
    const float* bn_g     = (const float*)d_in[9];
    const float* bn_b     = (const float*)d_in[10];
    const float* dist_w   = (const float*)d_in[11];
    const float* dist_b   = (const float*)d_in[12];
    const float* dec_w1   = (const float*)d_in[13];
    const float* dec_b1   = (const float*)d_in[14];
    const float* dec_bng  = (const float*)d_in[15];
    const float* dec_bnb  = (const float*)d_in[16];
    const float* dec_w2   = (const float*)d_in[17];
    const float* dec_b2   = (const float*)d_in[18];
    const int* x_idx      = (const int*)d_in[19];
    const int* edge_attr  = (const int*)d_in[20];
    const int* edge_index = (const int*)d_in[21];
    const int* batch      = (const int*)d_in[22];
    float* out = (float*)d_out;

    void* sp = nullptr;
    cudaGetSymbolAddress(&sp, g_scratch);
    float* S = (float*)sp;
    float* h     = S + OFF_H;
    float* z     = S + OFF_Z;
    float* z1    = S + OFF_Z1;
    float* z2    = S + OFF_Z2;
    float* hg    = S + OFF_HG;
    float* mu    = S + OFF_MU;
    float* zdec  = S + OFF_ZDEC;
    float* stats = S + OFF_STATS;
    float* bnA   = S + OFF_BNA;
    float* bnB   = S + OFF_BNB;

    const int TB = 256;
    const int gNode = (NNODE * D4 + TB - 1) / TB;
    const int gEdge = (NEDGE * D4 + TB - 1) / TB;

    // h = atom_emb[x_idx]
    k_gather<<<gNode, TB>>>(atom_emb, x_idx, h);

    for (int l = 0; l < NLAYER; l++) {
        // z = (1+eps[l])*h ; then scatter-add messages
        k_scale<<<gNode, TB>>>(h, eps, l, z);
        k_edge<<<gEdge, TB>>>(h, edge_emb + (size_t)l * 5 * D, edge_attr, edge_index, z);

        // z1 = z @ w1 + b1
        dim3 g1((HDIM + BN - 1) / BN, (NNODE + BM - 1) / BM);
        k_gemm<MODE_PLAIN><<<g1, 256>>>(z, conv_w1 + (size_t)l * D * HDIM,
                                        conv_b1 + (size_t)l * HDIM,
                                        z1, nullptr, nullptr,
                                        NNODE, HDIM, D, HDIM, HDIM, HDIM,
                                        nullptr, nullptr);
        // BN1 stats -> scale/shift
        k_zero<<<(2432 + TB - 1) / TB, TB>>>(stats, 2432);
        dim3 gr1((HDIM + TB - 1) / TB, (NNODE + RED_ROWS - 1) / RED_ROWS);
        k_colreduce<<<gr1, TB>>>(z1, NNODE, HDIM, stats);
        k_bnparam<<<(HDIM + TB - 1) / TB, TB>>>(stats, bn1g + (size_t)l * HDIM,
                                                bn1b + (size_t)l * HDIM,
                                                HDIM, 1.0f / NNODE, bnA, bnB);
        // z2 = relu(bn(z1)) @ w2 + b2
        dim3 g2((D + BN - 1) / BN, (NNODE + BM - 1) / BM);
        k_gemm<MODE_BNRELU><<<g2, 256>>>(z1, conv_w2 + (size_t)l * HDIM * D,
                                         conv_b2 + (size_t)l * D,
                                         z2, nullptr, nullptr,
                                         NNODE, D, HDIM, D, D, D,
                                         bnA, bnB);
        // BN2 stats -> scale/shift
        k_zero<<<(2432 + TB - 1) / TB, TB>>>(stats, 2432);
        dim3 gr2((D + TB - 1) / TB, (NNODE + RED_ROWS - 1) / RED_ROWS);
        k_colreduce<<<gr2, TB>>>(z2, NNODE, D, stats);
        k_bnparam<<<(D + TB - 1) / TB, TB>>>(stats, bn_g + (size_t)l * D,
                                             bn_b + (size_t)l * D,
                                             D, 1.0f / NNODE, bnA, bnB);
        // h = h + [relu](bn(z2))
        k_finalize<<<gNode, TB>>>(z2, bnA, bnB, (l < NLAYER - 1) ? 1 : 0, h);
    }

    // graph pooling: segment max
    k_hginit<<<(NGRAPH * D + TB - 1) / TB, TB>>>(hg);
    k_segmax<<<gNode, TB>>>(h, batch, hg);

    // d = silu(hg) @ dist_w + dist_b; mu -> out[0:], sigma -> out[G*D:]
    {
        dim3 gd((HDIM + BN - 1) / BN, (NGRAPH + BM - 1) / BM);
        k_gemm<MODE_DIST><<<gd, 256>>>(hg, dist_w, dist_b,
                                       out,                    // mu region
                                       out + (size_t)NGRAPH * D, // sigma region
                                       mu,
                                       NGRAPH, HDIM, D, HDIM, HDIM, D,
                                       nullptr, nullptr);
    }

    // decoders
    const int ddims[6] = {1024, 1111, 862, 1783, 966, 978};
    const size_t dbase[6] = {
        2457600ull,                 // out0
        6651904ull,                 // out1 (gene, offset 0)
        6651904ull + 1111ull,       // out2 (gene, offset 1111)
        14733312ull,                // out3 (cell, offset 0)
        14733312ull + 1783ull,      // out4 (cell, offset 1783)
        25993216ull                 // out5
    };
    const int dldc[6] = {1024, 1973, 1973, 2749, 2749, 978};

    for (int i = 0; i < 6; i++) {
        dim3 gd1((DECH + BN - 1) / BN, (NGRAPH + BM - 1) / BM);
        k_gemm<MODE_PLAIN><<<gd1, 256>>>(mu, dec_w1 + (size_t)i * D * DECH,
                                         dec_b1 + (size_t)i * DECH,
                                         zdec, nullptr, nullptr,
                                         NGRAPH, DECH, D, DECH, DECH, DECH,
                                         nullptr, nullptr);
        k_zero<<<(2432 + TB - 1) / TB, TB>>>(stats, 2432);
        dim3 grd((DECH + TB - 1) / TB, (NGRAPH + RED_ROWS - 1) / RED_ROWS);
        k_colreduce<<<grd, TB>>>(zdec, NGRAPH, DECH, stats);
        k_bnparam<<<(DECH + TB - 1) / TB, TB>>>(stats, dec_bng + (size_t)i * DECH,
                                                dec_bnb + (size_t)i * DECH,
                                                DECH, 1.0f / NGRAPH, bnA, bnB);
        dim3 gd2((ddims[i] + BN - 1) / BN, (NGRAPH + BM - 1) / BM);
        k_gemm<MODE_DEC><<<gd2, 256>>>(zdec, dec_w2 + (size_t)i * DECH * MAXO,
                                       dec_b2 + (size_t)i * MAXO,
                                       out + dbase[i], nullptr, nullptr,
                                       NGRAPH, ddims[i], DECH, MAXO, MAXO, dldc[i],
                                       bnA, bnB);
    }
}

// round 2
// speedup vs baseline: 1.2401x; 1.2401x over previous
#include <cuda_runtime.h>
#include <math.h>

#define NNODE 100000
#define NEDGE 200000
#define NGRAPH 4096
#define D 300
#define NLAYER 5
#define HDIM 600
#define DECH 1200
#define MAXO 1783
#define D4 (D/4)

// ---------------- scratch arena (no cudaMalloc allowed) ----------------
#define OFF_H     0ull
#define OFF_Z     30000000ull
#define OFF_Z1    60000000ull
#define OFF_Z2    120000000ull
#define OFF_HG    150000000ull
#define OFF_MU    151228800ull
#define OFF_ZDEC  152457600ull
#define OFF_STATS 157372800ull
#define OFF_BNA   157375232ull
#define OFF_BNB   157376448ull
#define SCRATCH_FLOATS 157377664ull

__device__ float g_scratch[SCRATCH_FLOATS];

// ---------------- small elementwise kernels ----------------

__global__ void k_gather(const float* __restrict__ atom_emb,
                         const int* __restrict__ x_idx,
                         float* __restrict__ h) {
    int t = blockIdx.x * blockDim.x + threadIdx.x;
    if (t >= NNODE * D4) return;
    int i = t / D4;
    int c = (t - i * D4) * 4;
    int a = x_idx[i];
    float4 v = *reinterpret_cast<const float4*>(atom_emb + (size_t)a * D + c);
    *reinterpret_cast<float4*>(h + (size_t)i * D + c) = v;
}

__global__ void k_scale(const float* __restrict__ h,
                        const float* __restrict__ eps, int l,
                        float* __restrict__ z) {
    int t = blockIdx.x * blockDim.x + threadIdx.x;
    if (t >= NNODE * D4) return;
    float s = 1.0f + eps[l];
    float4 v = *reinterpret_cast<const float4*>(h + (size_t)t * 4);
    v.x *= s; v.y *= s; v.z *= s; v.w *= s;
    *reinterpret_cast<float4*>(z + (size_t)t * 4) = v;
}

__global__ void k_edge(const float* __restrict__ h,
                       const float* __restrict__ emb,
                       const int* __restrict__ attr,
                       const int* __restrict__ eidx,
                       float* __restrict__ z) {
    int t = blockIdx.x * blockDim.x + threadIdx.x;
    if (t >= NEDGE * D4) return;
    int e = t / D4;
    int c = (t - e * D4) * 4;
    int src = eidx[e];
    int dst = eidx[NEDGE + e];
    int a = attr[e];
    float4 hv = *reinterpret_cast<const float4*>(h + (size_t)src * D + c);
    float4 ev = *reinterpret_cast<const float4*>(emb + (size_t)a * D + c);
    float m0 = fmaxf(hv.x + ev.x, 0.0f);
    float m1 = fmaxf(hv.y + ev.y, 0.0f);
    float m2 = fmaxf(hv.z + ev.z, 0.0f);
    float m3 = fmaxf(hv.w + ev.w, 0.0f);
    float* zp = z + (size_t)dst * D + c;
    atomicAdd(zp + 0, m0);
    atomicAdd(zp + 1, m1);
    atomicAdd(zp + 2, m2);
    atomicAdd(zp + 3, m3);
}

__global__ void k_zero(float* __restrict__ p, int n) {
    int t = blockIdx.x * blockDim.x + threadIdx.x;
    if (t < n) p[t] = 0.0f;
}

#define RED_ROWS 512
__global__ void k_colreduce(const float* __restrict__ X, int M, int Nc,
                            float* __restrict__ stats) {
    int c = blockIdx.x * blockDim.x + threadIdx.x;
    if (c >= Nc) return;
    int r0 = blockIdx.y * RED_ROWS;
    int r1 = r0 + RED_ROWS; if (r1 > M) r1 = M;
    float s = 0.0f, s2 = 0.0f;
    for (int r = r0; r < r1; r++) {
        float v = X[(size_t)r * Nc + c];
        s += v;
        s2 += v * v;
    }
    atomicAdd(&stats[c], s);
    atomicAdd(&stats[Nc + c], s2);
}

__global__ void k_bnparam(const float* __restrict__ stats,
                          const float* __restrict__ g,
                          const float* __restrict__ b,
                          int Nc, float invM,
                          float* __restrict__ bnA, float* __restrict__ bnB) {
    int c = blockIdx.x * blockDim.x + threadIdx.x;
    if (c >= Nc) return;
    float mean = stats[c] * invM;
    float var = stats[Nc + c] * invM - mean * mean;
    float a = g[c] * rsqrtf(var + 1e-5f);
    bnA[c] = a;
    bnB[c] = b[c] - mean * a;
}

__global__ void k_finalize(const float* __restrict__ z2,
                           const float* __restrict__ bnA,
                           const float* __restrict__ bnB,
                           int dorelu, float* __restrict__ h) {
    int t = blockIdx.x * blockDim.x + threadIdx.x;
    if (t >= NNODE * D4) return;
    size_t base = (size_t)t * 4;
    int c = (int)(base % D);
    float4 zv = *reinterpret_cast<const float4*>(z2 + base);
    float4 hv = *reinterpret_cast<const float4*>(h + base);
    float v0 = bnA[c + 0] * zv.x + bnB[c + 0];
    float v1 = bnA[c + 1] * zv.y + bnB[c + 1];
    float v2 = bnA[c + 2] * zv.z + bnB[c + 2];
    float v3 = bnA[c + 3] * zv.w + bnB[c + 3];
    if (dorelu) {
        v0 = fmaxf(v0, 0.0f); v1 = fmaxf(v1, 0.0f);
        v2 = fmaxf(v2, 0.0f); v3 = fmaxf(v3, 0.0f);
    }
    hv.x += v0; hv.y += v1; hv.z += v2; hv.w += v3;
    *reinterpret_cast<float4*>(h + base) = hv;
}

__global__ void k_hginit(float* __restrict__ hg) {
    int t = blockIdx.x * blockDim.x + threadIdx.x;
    if (t < NGRAPH * D) hg[t] = -INFINITY;
}

__device__ __forceinline__ void atomicMaxF(float* addr, float v) {
    if (v >= 0.0f) atomicMax((int*)addr, __float_as_int(v));
    else atomicMin((unsigned int*)addr, __float_as_uint(v));
}

__global__ void k_segmax(const float* __restrict__ h,
                         const int* __restrict__ batch,
                         float* __restrict__ hg) {
    int t = blockIdx.x * blockDim.x + threadIdx.x;
    if (t >= NNODE * D4) return;
    int i = t / D4;
    int c = (t - i * D4) * 4;
    int g = batch[i];
    float4 v = *reinterpret_cast<const float4*>(h + (size_t)i * D + c);
    float* p = hg + (size_t)g * D + c;
    atomicMaxF(p + 0, v.x);
    atomicMaxF(p + 1, v.y);
    atomicMaxF(p + 2, v.z);
    atomicMaxF(p + 3, v.w);
}

// ---------------- GEMM: 128x128x8, double-buffered, 256 threads, 8x8/thread ----
// MODE 0: C = A@B + bias
// MODE 1: C = relu(bnA*A + bnB) @ B + bias
// MODE 2: C = silu(A)@B + bias; col<D -> C and C3; col>=D -> softplus+1e-7 -> C2
// MODE 3: C = gelu(bnA*A + bnB) @ B + bias; store col<N with row stride ldc

#define MODE_PLAIN 0
#define MODE_BNRELU 1
#define MODE_DIST 2
#define MODE_DEC 3

#define BM 128
#define BN 128
#define BK 8

template <int MODE>
__device__ __forceinline__ void preprocA(float4& av, int gk,
                                         const float* __restrict__ bnA,
                                         const float* __restrict__ bnB) {
    if (MODE == MODE_BNRELU) {
        av.x = fmaxf(fmaf(bnA[gk + 0], av.x, bnB[gk + 0]), 0.0f);
        av.y = fmaxf(fmaf(bnA[gk + 1], av.y, bnB[gk + 1]), 0.0f);
        av.z = fmaxf(fmaf(bnA[gk + 2], av.z, bnB[gk + 2]), 0.0f);
        av.w = fmaxf(fmaf(bnA[gk + 3], av.w, bnB[gk + 3]), 0.0f);
    } else if (MODE == MODE_DIST) {
        av.x = av.x / (1.0f + expf(-av.x));
        av.y = av.y / (1.0f + expf(-av.y));
        av.z = av.z / (1.0f + expf(-av.z));
        av.w = av.w / (1.0f + expf(-av.w));
    } else if (MODE == MODE_DEC) {
        float t0 = fmaf(bnA[gk + 0], av.x, bnB[gk + 0]);
        float t1 = fmaf(bnA[gk + 1], av.y, bnB[gk + 1]);
        float t2 = fmaf(bnA[gk + 2], av.z, bnB[gk + 2]);
        float t3 = fmaf(bnA[gk + 3], av.w, bnB[gk + 3]);
        av.x = 0.5f * t0 * (1.0f + erff(t0 * 0.70710678118654752f));
        av.y = 0.5f * t1 * (1.0f + erff(t1 * 0.70710678118654752f));
        av.z = 0.5f * t2 * (1.0f + erff(t2 * 0.70710678118654752f));
        av.w = 0.5f * t3 * (1.0f + erff(t3 * 0.70710678118654752f));
    }
}

template <int MODE, bool VECB>
__global__ void __launch_bounds__(256, 2)
k_gemm(const float* __restrict__ A, const float* __restrict__ B,
       const float* __restrict__ bias,
       float* __restrict__ C, float* __restrict__ C2, float* __restrict__ C3,
       int M, int N, int K, int ldb, int NB, int ldc,
       const float* __restrict__ bnA, const float* __restrict__ bnB) {
    __shared__ __align__(16) float As[2][BK][BM];
    __shared__ __align__(16) float Bs[2][BK][BN];
    int tid = threadIdx.x;
    int row0 = blockIdx.y * BM;
    int col0 = blockIdx.x * BN;
    int tx = tid & 15, ty = tid >> 4;

    int arow = tid >> 1;          // 0..127
    int ak = (tid & 1) << 2;      // 0 or 4
    int bkr = tid >> 5;           // 0..7
    int bc = (tid & 31) << 2;     // 0..124

    int gr = row0 + arow;
    bool rowok = (gr < M);
    const float* Arow = A + (size_t)gr * K;

    float acc[8][8];
#pragma unroll
    for (int i = 0; i < 8; i++)
#pragma unroll
        for (int j = 0; j < 8; j++) acc[i][j] = 0.0f;

    const int ktiles = (K + BK - 1) / BK;

    // --- prologue: fetch tile 0 ---
    float4 av;
    float bv0, bv1, bv2, bv3;
    {
        int gk = ak;  // tile 0
        av = make_float4(0.f, 0.f, 0.f, 0.f);
        if (rowok && gk < K) {
            av = *reinterpret_cast<const float4*>(Arow + gk);
            preprocA<MODE>(av, gk, bnA, bnB);
        }
        int gkb = bkr;
        if (VECB) {
            float4 b4 = make_float4(0.f, 0.f, 0.f, 0.f);
            if (gkb < K && (col0 + bc) < NB)
                b4 = *reinterpret_cast<const float4*>(B + (size_t)gkb * ldb + col0 + bc);
            bv0 = b4.x; bv1 = b4.y; bv2 = b4.z; bv3 = b4.w;
        } else {
            const float* Bp = B + (size_t)gkb * ldb + col0 + bc;
            bool kok = (gkb < K);
            bv0 = (kok && col0 + bc + 0 < NB) ? Bp[0] : 0.0f;
            bv1 = (kok && col0 + bc + 1 < NB) ? Bp[1] : 0.0f;
            bv2 = (kok && col0 + bc + 2 < NB) ? Bp[2] : 0.0f;
            bv3 = (kok && col0 + bc + 3 < NB) ? Bp[3] : 0.0f;
        }
    }
    As[0][ak + 0][arow] = av.x;
    As[0][ak + 1][arow] = av.y;
    As[0][ak + 2][arow] = av.z;
    As[0][ak + 3][arow] = av.w;
    Bs[0][bkr][bc + 0] = bv0;
    Bs[0][bkr][bc + 1] = bv1;
    Bs[0][bkr][bc + 2] = bv2;
    Bs[0][bkr][bc + 3] = bv3;
    __syncthreads();

    int buf = 0;
    for (int t = 0; t < ktiles; t++) {
        bool has = (t + 1 < ktiles);
        // prefetch next tile into registers (overlapped with compute below)
        if (has) {
            int gk = (t + 1) * BK + ak;
            av = make_float4(0.f, 0.f, 0.f, 0.f);
            if (rowok && gk < K) {
                av = *reinterpret_cast<const float4*>(Arow + gk);
                preprocA<MODE>(av, gk, bnA, bnB);
            }
            int gkb = (t + 1) * BK + bkr;
            if (VECB) {
                float4 b4 = make_float4(0.f, 0.f, 0.f, 0.f);
                if (gkb < K && (col0 + bc) < NB)
                    b4 = *reinterpret_cast<const float4*>(B + (size_t)gkb * ldb + col0 + bc);
                bv0 = b4.x; bv1 = b4.y; bv2 = b4.z; bv3 = b4.w;
            } else {
                const float* Bp = B + (size_t)gkb * ldb + col0 + bc;
                bool kok = (gkb < K);
                bv0 = (kok && col0 + bc + 0 < NB) ? Bp[0] : 0.0f;
                bv1 = (kok && col0 + bc + 1 < NB) ? Bp[1] : 0.0f;
                bv2 = (kok && col0 + bc + 2 < NB) ? Bp[2] : 0.0f;
                bv3 = (kok && col0 + bc + 3 < NB) ? Bp[3] : 0.0f;
            }
        }

        // compute on smem[buf]
#pragma unroll
        for (int kk = 0; kk < BK; kk++) {
            float4 a0 = *reinterpret_cast<const float4*>(&As[buf][kk][ty * 8]);
            float4 a1 = *reinterpret_cast<const float4*>(&As[buf][kk][ty * 8 + 4]);
            float4 b0 = *reinterpret_cast<const float4*>(&Bs[buf][kk][tx * 8]);
            float4 b1 = *reinterpret_cast<const float4*>(&Bs[buf][kk][tx * 8 + 4]);
            float a[8] = {a0.x, a0.y, a0.z, a0.w, a1.x, a1.y, a1.z, a1.w};
            float b[8] = {b0.x, b0.y, b0.z, b0.w, b1.x, b1.y, b1.z, b1.w};
#pragma unroll
            for (int i = 0; i < 8; i++)
#pragma unroll
                for (int j = 0; j < 8; j++)
                    acc[i][j] = fmaf(a[i], b[j], acc[i][j]);
        }

        if (has) {
            int nb = buf ^ 1;
            As[nb][ak + 0][arow] = av.x;
            As[nb][ak + 1][arow] = av.y;
            As[nb][ak + 2][arow] = av.z;
            As[nb][ak + 3][arow] = av.w;
            Bs[nb][bkr][bc + 0] = bv0;
            Bs[nb][bkr][bc + 1] = bv1;
            Bs[nb][bkr][bc + 2] = bv2;
            Bs[nb][bkr][bc + 3] = bv3;
            __syncthreads();
            buf = nb;
        }
    }

    // epilogue
#pragma unroll
    for (int i = 0; i < 8; i++) {
        int r = row0 + ty * 8 + i;
        if (r >= M) continue;
#pragma unroll
        for (int j = 0; j < 8; j++) {
            int c = col0 + tx * 8 + j;
            if (c >= N) continue;
            float v = acc[i][j] + bias[c];
            if (MODE == MODE_DIST) {
                if (c < D) {
                    C[(size_t)r * ldc + c] = v;
                    C3[(size_t)r * D + c] = v;
                } else {
                    float sp = fmaxf(v, 0.0f) + log1pf(expf(-fabsf(v))) + 1e-7f;
                    C2[(size_t)r * ldc + (c - D)] = sp;
                }
            } else {
                C[(size_t)r * ldc + c] = v;
            }
        }
    }
}

// ---------------- host side ----------------

extern "C" void kernel_launch(void* const* d_in, const int* in_sizes, int n_in,
                              void* d_out, int out_size) {
    const float* atom_emb = (const float*)d_in[0];
    const float* edge_emb = (const float*)d_in[1];
    const float* eps      = (const float*)d_in[2];
    const float* conv_w1  = (const float*)d_in[3];
    const float* conv_b1  = (const float*)d_in[4];
    const float* bn1g     = (const float*)d_in[5];
    const float* bn1b     = (const float*)d_in[6];
    const float* conv_w2  = (const float*)d_in[7];
    const float* conv_b2  = (const float*)d_in[8];
    const float* bn_g     = (const float*)d_in[9];
    const float* bn_b     = (const float*)d_in[10];
    const float* dist_w   = (const float*)d_in[11];
    const float* dist_b   = (const float*)d_in[12];
    const float* dec_w1   = (const float*)d_in[13];
    const float* dec_b1   = (const float*)d_in[14];
    const float* dec_bng  = (const float*)d_in[15];
    const float* dec_bnb  = (const float*)d_in[16];
    const float* dec_w2   = (const float*)d_in[17];
    const float* dec_b2   = (const float*)d_in[18];
    const int* x_idx      = (const int*)d_in[19];
    const int* edge_attr  = (const int*)d_in[20];
    const int* edge_index = (const int*)d_in[21];
    const int* batch      = (const int*)d_in[22];
    float* out = (float*)d_out;

    void* sp = nullptr;
    cudaGetSymbolAddress(&sp, g_scratch);
    float* S = (float*)sp;
    float* h     = S + OFF_H;
    float* z     = S + OFF_Z;
    float* z1    = S + OFF_Z1;
    float* z2    = S + OFF_Z2;
    float* hg    = S + OFF_HG;
    float* mu    = S + OFF_MU;
    float* zdec  = S + OFF_ZDEC;
    float* stats = S + OFF_STATS;
    float* bnA   = S + OFF_BNA;
    float* bnB   = S + OFF_BNB;

    const int TB = 256;
    const int gNode = (NNODE * D4 + TB - 1) / TB;
    const int gEdge = (NEDGE * D4 + TB - 1) / TB;

    k_gather<<<gNode, TB>>>(atom_emb, x_idx, h);

    for (int l = 0; l < NLAYER; l++) {
        k_scale<<<gNode, TB>>>(h, eps, l, z);
        k_edge<<<gEdge, TB>>>(h, edge_emb + (size_t)l * 5 * D, edge_attr, edge_index, z);

        dim3 g1((HDIM + BN - 1) / BN, (NNODE + BM - 1) / BM);
        k_gemm<MODE_PLAIN, true><<<g1, 256>>>(z, conv_w1 + (size_t)l * D * HDIM,
                                        conv_b1 + (size_t)l * HDIM,
                                        z1, nullptr, nullptr,
                                        NNODE, HDIM, D, HDIM, HDIM, HDIM,
                                        nullptr, nullptr);
        k_zero<<<(2432 + TB - 1) / TB, TB>>>(stats, 2432);
        dim3 gr1((HDIM + TB - 1) / TB, (NNODE + RED_ROWS - 1) / RED_ROWS);
        k_colreduce<<<gr1, TB>>>(z1, NNODE, HDIM, stats);
        k_bnparam<<<(HDIM + TB - 1) / TB, TB>>>(stats, bn1g + (size_t)l * HDIM,
                                                bn1b + (size_t)l * HDIM,
                                                HDIM, 1.0f / NNODE, bnA, bnB);
        dim3 g2((D + BN - 1) / BN, (NNODE + BM - 1) / BM);
        k_gemm<MODE_BNRELU, true><<<g2, 256>>>(z1, conv_w2 + (size_t)l * HDIM * D,
                                         conv_b2 + (size_t)l * D,
                                         z2, nullptr, nullptr,
                                         NNODE, D, HDIM, D, D, D,
                                         bnA, bnB);
        k_zero<<<(2432 + TB - 1) / TB, TB>>>(stats, 2432);
        dim3 gr2((D + TB - 1) / TB, (NNODE + RED_ROWS - 1) / RED_ROWS);
        k_colreduce<<<gr2, TB>>>(z2, NNODE, D, stats);
        k_bnparam<<<(D + TB - 1) / TB, TB>>>(stats, bn_g + (size_t)l * D,
                                             bn_b + (size_t)l * D,
                                             D, 1.0f / NNODE, bnA, bnB);
        k_finalize<<<gNode, TB>>>(z2, bnA, bnB, (l < NLAYER - 1) ? 1 : 0, h);
    }

    k_hginit<<<(NGRAPH * D + TB - 1) / TB, TB>>>(hg);
    k_segmax<<<gNode, TB>>>(h, batch, hg);

    {
        dim3 gd((HDIM + BN - 1) / BN, (NGRAPH + BM - 1) / BM);
        k_gemm<MODE_DIST, true><<<gd, 256>>>(hg, dist_w, dist_b,
                                       out,
                                       out + (size_t)NGRAPH * D,
                                       mu,
                                       NGRAPH, HDIM, D, HDIM, HDIM, D,
                                       nullptr, nullptr);
    }

    const int ddims[6] = {1024, 1111, 862, 1783, 966, 978};
    const size_t dbase[6] = {
        2457600ull,
        6651904ull,
        6651904ull + 1111ull,
        14733312ull,
        14733312ull + 1783ull,
        25993216ull
    };
    const int dldc[6] = {1024, 1973, 1973, 2749, 2749, 978};

    for (int i = 0; i < 6; i++) {
        dim3 gd1((DECH + BN - 1) / BN, (NGRAPH + BM - 1) / BM);
        k_gemm<MODE_PLAIN, true><<<gd1, 256>>>(mu, dec_w1 + (size_t)i * D * DECH,
                                         dec_b1 + (size_t)i * DECH,
                                         zdec, nullptr, nullptr,
                                         NGRAPH, DECH, D, DECH, DECH, DECH,
                                         nullptr, nullptr);
        k_zero<<<(2432 + TB - 1) / TB, TB>>>(stats, 2432);
        dim3 grd((DECH + TB - 1) / TB, (NGRAPH + RED_ROWS - 1) / RED_ROWS);
        k_colreduce<<<grd, TB>>>(zdec, NGRAPH, DECH, stats);
        k_bnparam<<<(DECH + TB - 1) / TB, TB>>>(stats, dec_bng + (size_t)i * DECH,
                                                dec_bnb + (size_t)i * DECH,
                                                DECH, 1.0f / NGRAPH, bnA, bnB);
        dim3 gd2((ddims[i] + BN - 1) / BN, (NGRAPH + BM - 1) / BM);
        k_gemm<MODE_DEC, false><<<gd2, 256>>>(zdec, dec_w2 + (size_t)i * DECH * MAXO,
                                       dec_b2 + (size_t)i * MAXO,
                                       out + dbase[i], nullptr, nullptr,
                                       NGRAPH, ddims[i], DECH, MAXO, MAXO, dldc[i],
                                       bnA, bnB);
    }
}

// round 5
// speedup vs baseline: 1.2611x; 1.0169x over previous
#include <cuda_runtime.h>
#include <math.h>
#include <stdint.h>

#define NNODE 100000
#define NEDGE 200000
#define NGRAPH 4096
#define D 300
#define NLAYER 5
#define HDIM 600
#define DECH 1200
#define MAXO 1783
#define D4 (D/4)

// ---------------- scratch arena (no cudaMalloc allowed) ----------------
#define OFF_H     0ull
#define OFF_Z     30000000ull
#define OFF_Z1    60000000ull
#define OFF_Z2    120000000ull
#define OFF_HG    150000000ull
#define OFF_MU    151228800ull
#define OFF_ZDEC  152457600ull
#define OFF_STATS 157372800ull
#define OFF_BNA   157375232ull
#define OFF_BNB   157376448ull
#define SCRATCH_FLOATS 157377664ull

__device__ float g_scratch[SCRATCH_FLOATS];

// packed f32x2 helpers (base sm_100+ PTX, not 'a'-gated)
typedef unsigned long long u64;

#define FMA2(acc, a2, b2) \
    asm("fma.rn.f32x2 %0, %1, %2, %0;" : "+l"(acc) : "l"(a2), "l"(b2))
#define DUP2(d, x) \
    asm("mov.b64 %0, {%1, %1};" : "=l"(d) : "f"(x))
#define UNPACK2(lo, hi, v) \
    asm("mov.b64 {%0, %1}, %2;" : "=f"(lo), "=f"(hi) : "l"(v))

// ---------------- small elementwise kernels ----------------

__global__ void k_gather(const float* __restrict__ atom_emb,
                         const int* __restrict__ x_idx,
                         float* __restrict__ h) {
    int t = blockIdx.x * blockDim.x + threadIdx.x;
    if (t >= NNODE * D4) return;
    int i = t / D4;
    int c = (t - i * D4) * 4;
    int a = x_idx[i];
    float4 v = *reinterpret_cast<const float4*>(atom_emb + (size_t)a * D + c);
    *reinterpret_cast<float4*>(h + (size_t)i * D + c) = v;
}

__global__ void k_scale(const float* __restrict__ h,
                        const float* __restrict__ eps, int l,
                        float* __restrict__ z) {
    int t = blockIdx.x * blockDim.x + threadIdx.x;
    if (t >= NNODE * D4) return;
    float s = 1.0f + eps[l];
    float4 v = *reinterpret_cast<const float4*>(h + (size_t)t * 4);
    v.x *= s; v.y *= s; v.z *= s; v.w *= s;
    *reinterpret_cast<float4*>(z + (size_t)t * 4) = v;
}

__global__ void k_edge(const float* __restrict__ h,
                       const float* __restrict__ emb,
                       const int* __restrict__ attr,
                       const int* __restrict__ eidx,
                       float* __restrict__ z) {
    int t = blockIdx.x * blockDim.x + threadIdx.x;
    if (t >= NEDGE * D4) return;
    int e = t / D4;
    int c = (t - e * D4) * 4;
    int src = eidx[e];
    int dst = eidx[NEDGE + e];
    int a = attr[e];
    float4 hv = *reinterpret_cast<const float4*>(h + (size_t)src * D + c);
    float4 ev = *reinterpret_cast<const float4*>(emb + (size_t)a * D + c);
    float m0 = fmaxf(hv.x + ev.x, 0.0f);
    float m1 = fmaxf(hv.y + ev.y, 0.0f);
    float m2 = fmaxf(hv.z + ev.z, 0.0f);
    float m3 = fmaxf(hv.w + ev.w, 0.0f);
    float* zp = z + (size_t)dst * D + c;
    atomicAdd(zp + 0, m0);
    atomicAdd(zp + 1, m1);
    atomicAdd(zp + 2, m2);
    atomicAdd(zp + 3, m3);
}

__global__ void k_zero(float* __restrict__ p, int n) {
    int t = blockIdx.x * blockDim.x + threadIdx.x;
    if (t < n) p[t] = 0.0f;
}

#define RED_ROWS 512
__global__ void k_colreduce(const float* __restrict__ X, int M, int Nc,
                            float* __restrict__ stats) {
    int c = blockIdx.x * blockDim.x + threadIdx.x;
    if (c >= Nc) return;
    int r0 = blockIdx.y * RED_ROWS;
    int r1 = r0 + RED_ROWS; if (r1 > M) r1 = M;
    float s = 0.0f, s2 = 0.0f;
    for (int r = r0; r < r1; r++) {
        float v = X[(size_t)r * Nc + c];
        s += v;
        s2 += v * v;
    }
    atomicAdd(&stats[c], s);
    atomicAdd(&stats[Nc + c], s2);
}

__global__ void k_bnparam(const float* __restrict__ stats,
                          const float* __restrict__ g,
                          const float* __restrict__ b,
                          int Nc, float invM,
                          float* __restrict__ bnA, float* __restrict__ bnB) {
    int c = blockIdx.x * blockDim.x + threadIdx.x;
    if (c >= Nc) return;
    float mean = stats[c] * invM;
    float var = stats[Nc + c] * invM - mean * mean;
    float a = g[c] * rsqrtf(var + 1e-5f);
    bnA[c] = a;
    bnB[c] = b[c] - mean * a;
}

__global__ void k_finalize(const float* __restrict__ z2,
                           const float* __restrict__ bnA,
                           const float* __restrict__ bnB,
                           int dorelu, float* __restrict__ h) {
    int t = blockIdx.x * blockDim.x + threadIdx.x;
    if (t >= NNODE * D4) return;
    size_t base = (size_t)t * 4;
    int c = (int)(base % D);
    float4 zv = *reinterpret_cast<const float4*>(z2 + base);
    float4 hv = *reinterpret_cast<const float4*>(h + base);
    float v0 = bnA[c + 0] * zv.x + bnB[c + 0];
    float v1 = bnA[c + 1] * zv.y + bnB[c + 1];
    float v2 = bnA[c + 2] * zv.z + bnB[c + 2];
    float v3 = bnA[c + 3] * zv.w + bnB[c + 3];
    if (dorelu) {
        v0 = fmaxf(v0, 0.0f); v1 = fmaxf(v1, 0.0f);
        v2 = fmaxf(v2, 0.0f); v3 = fmaxf(v3, 0.0f);
    }
    hv.x += v0; hv.y += v1; hv.z += v2; hv.w += v3;
    *reinterpret_cast<float4*>(h + base) = hv;
}

__global__ void k_hginit(float* __restrict__ hg) {
    int t = blockIdx.x * blockDim.x + threadIdx.x;
    if (t < NGRAPH * D) hg[t] = -INFINITY;
}

__device__ __forceinline__ void atomicMaxF(float* addr, float v) {
    if (v >= 0.0f) atomicMax((int*)addr, __float_as_int(v));
    else atomicMin((unsigned int*)addr, __float_as_uint(v));
}

__global__ void k_segmax(const float* __restrict__ h,
                         const int* __restrict__ batch,
                         float* __restrict__ hg) {
    int t = blockIdx.x * blockDim.x + threadIdx.x;
    if (t >= NNODE * D4) return;
    int i = t / D4;
    int c = (t - i * D4) * 4;
    int g = batch[i];
    float4 v = *reinterpret_cast<const float4*>(h + (size_t)i * D + c);
    float* p = hg + (size_t)g * D + c;
    atomicMaxF(p + 0, v.x);
    atomicMaxF(p + 1, v.y);
    atomicMaxF(p + 2, v.z);
    atomicMaxF(p + 3, v.w);
}

// ---------------- GEMM: 128x128x8, double-buffered, packed f32x2 FMA ----------
// MODE 0: C = A@B + bias
// MODE 1: C = relu(bnA*A + bnB) @ B + bias
// MODE 2: C = silu(A)@B + bias; col<D -> C and C3; col>=D -> softplus+1e-7 -> C2
// MODE 3: C = gelu(bnA*A + bnB) @ B + bias; store col<N with row stride ldc

#define MODE_PLAIN 0
#define MODE_BNRELU 1
#define MODE_DIST 2
#define MODE_DEC 3

#define BM 128
#define BN 128
#define BK 8

template <int MODE>
__device__ __forceinline__ void preprocA(float4& av, int gk,
                                         const float* __restrict__ bnA,
                                         const float* __restrict__ bnB) {
    if (MODE == MODE_BNRELU) {
        av.x = fmaxf(fmaf(bnA[gk + 0], av.x, bnB[gk + 0]), 0.0f);
        av.y = fmaxf(fmaf(bnA[gk + 1], av.y, bnB[gk + 1]), 0.0f);
        av.z = fmaxf(fmaf(bnA[gk + 2], av.z, bnB[gk + 2]), 0.0f);
        av.w = fmaxf(fmaf(bnA[gk + 3], av.w, bnB[gk + 3]), 0.0f);
    } else if (MODE == MODE_DIST) {
        av.x = av.x / (1.0f + expf(-av.x));
        av.y = av.y / (1.0f + expf(-av.y));
        av.z = av.z / (1.0f + expf(-av.z));
        av.w = av.w / (1.0f + expf(-av.w));
    } else if (MODE == MODE_DEC) {
        float t0 = fmaf(bnA[gk + 0], av.x, bnB[gk + 0]);
        float t1 = fmaf(bnA[gk + 1], av.y, bnB[gk + 1]);
        float t2 = fmaf(bnA[gk + 2], av.z, bnB[gk + 2]);
        float t3 = fmaf(bnA[gk + 3], av.w, bnB[gk + 3]);
        av.x = 0.5f * t0 * (1.0f + erff(t0 * 0.70710678118654752f));
        av.y = 0.5f * t1 * (1.0f + erff(t1 * 0.70710678118654752f));
        av.z = 0.5f * t2 * (1.0f + erff(t2 * 0.70710678118654752f));
        av.w = 0.5f * t3 * (1.0f + erff(t3 * 0.70710678118654752f));
    }
}

template <int MODE, bool VECB>
__global__ void __launch_bounds__(256, 2)
k_gemm(const float* __restrict__ A, const float* __restrict__ B,
       const float* __restrict__ bias,
       float* __restrict__ C, float* __restrict__ C2, float* __restrict__ C3,
       int M, int N, int K, int ldb, int NB, int ldc,
       const float* __restrict__ bnA, const float* __restrict__ bnB) {
    __shared__ __align__(16) float As[2][BK][BM];
    __shared__ __align__(16) float Bs[2][BK][BN];
    int tid = threadIdx.x;
    int row0 = blockIdx.y * BM;
    int col0 = blockIdx.x * BN;
    int tx = tid & 15, ty = tid >> 4;

    int arow = tid >> 1;          // 0..127
    int ak = (tid & 1) << 2;      // 0 or 4
    int bkr = tid >> 5;           // 0..7
    int bc = (tid & 31) << 2;     // 0..124

    int gr = row0 + arow;
    bool rowok = (gr < M);
    const float* Arow = A + (size_t)gr * K;

    // packed accumulators: 8 rows x 4 column-pairs
    u64 acc2[8][4];
#pragma unroll
    for (int i = 0; i < 8; i++)
#pragma unroll
        for (int j = 0; j < 4; j++) acc2[i][j] = 0ull;

    const int ktiles = (K + BK - 1) / BK;

    // --- prologue: fetch tile 0 ---
    float4 av;
    float bv0, bv1, bv2, bv3;
    {
        int gk = ak;
        av = make_float4(0.f, 0.f, 0.f, 0.f);
        if (rowok && gk < K) {
            av = *reinterpret_cast<const float4*>(Arow + gk);
            preprocA<MODE>(av, gk, bnA, bnB);
        }
        int gkb = bkr;
        if (VECB) {
            float4 b4 = make_float4(0.f, 0.f, 0.f, 0.f);
            if (gkb < K && (col0 + bc) < NB)
                b4 = *reinterpret_cast<const float4*>(B + (size_t)gkb * ldb + col0 + bc);
            bv0 = b4.x; bv1 = b4.y; bv2 = b4.z; bv3 = b4.w;
        } else {
            const float* Bp = B + (size_t)gkb * ldb + col0 + bc;
            bool kok = (gkb < K);
            bv0 = (kok && col0 + bc + 0 < NB) ? Bp[0] : 0.0f;
            bv1 = (kok && col0 + bc + 1 < NB) ? Bp[1] : 0.0f;
            bv2 = (kok && col0 + bc + 2 < NB) ? Bp[2] : 0.0f;
            bv3 = (kok && col0 + bc + 3 < NB) ? Bp[3] : 0.0f;
        }
    }
    As[0][ak + 0][arow] = av.x;
    As[0][ak + 1][arow] = av.y;
    As[0][ak + 2][arow] = av.z;
    As[0][ak + 3][arow] = av.w;
    Bs[0][bkr][bc + 0] = bv0;
    Bs[0][bkr][bc + 1] = bv1;
    Bs[0][bkr][bc + 2] = bv2;
    Bs[0][bkr][bc + 3] = bv3;
    __syncthreads();

    int buf = 0;
    for (int t = 0; t < ktiles; t++) {
        bool has = (t + 1 < ktiles);
        if (has) {
            int gk = (t + 1) * BK + ak;
            av = make_float4(0.f, 0.f, 0.f, 0.f);
            if (rowok && gk < K) {
                av = *reinterpret_cast<const float4*>(Arow + gk);
                preprocA<MODE>(av, gk, bnA, bnB);
            }
            int gkb = (t + 1) * BK + bkr;
            if (VECB) {
                float4 b4 = make_float4(0.f, 0.f, 0.f, 0.f);
                if (gkb < K && (col0 + bc) < NB)
                    b4 = *reinterpret_cast<const float4*>(B + (size_t)gkb * ldb + col0 + bc);
                bv0 = b4.x; bv1 = b4.y; bv2 = b4.z; bv3 = b4.w;
            } else {
                const float* Bp = B + (size_t)gkb * ldb + col0 + bc;
                bool kok = (gkb < K);
                bv0 = (kok && col0 + bc + 0 < NB) ? Bp[0] : 0.0f;
                bv1 = (kok && col0 + bc + 1 < NB) ? Bp[1] : 0.0f;
                bv2 = (kok && col0 + bc + 2 < NB) ? Bp[2] : 0.0f;
                bv3 = (kok && col0 + bc + 3 < NB) ? Bp[3] : 0.0f;
            }
        }

        // compute on smem[buf] with packed f32x2 FMA
#pragma unroll
        for (int kk = 0; kk < BK; kk++) {
            float4 a0 = *reinterpret_cast<const float4*>(&As[buf][kk][ty * 8]);
            float4 a1 = *reinterpret_cast<const float4*>(&As[buf][kk][ty * 8 + 4]);
            ulonglong2 bq0 = *reinterpret_cast<const ulonglong2*>(&Bs[buf][kk][tx * 8]);
            ulonglong2 bq1 = *reinterpret_cast<const ulonglong2*>(&Bs[buf][kk][tx * 8 + 4]);
            u64 b2[4] = {bq0.x, bq0.y, bq1.x, bq1.y};
            float a[8] = {a0.x, a0.y, a0.z, a0.w, a1.x, a1.y, a1.z, a1.w};
#pragma unroll
            for (int i = 0; i < 8; i++) {
                u64 a2;
                DUP2(a2, a[i]);
#pragma unroll
                for (int j = 0; j < 4; j++)
                    FMA2(acc2[i][j], a2, b2[j]);
            }
        }

        if (has) {
            int nb = buf ^ 1;
            As[nb][ak + 0][arow] = av.x;
            As[nb][ak + 1][arow] = av.y;
            As[nb][ak + 2][arow] = av.z;
            As[nb][ak + 3][arow] = av.w;
            Bs[nb][bkr][bc + 0] = bv0;
            Bs[nb][bkr][bc + 1] = bv1;
            Bs[nb][bkr][bc + 2] = bv2;
            Bs[nb][bkr][bc + 3] = bv3;
            __syncthreads();
            buf = nb;
        }
    }

    // epilogue
#pragma unroll
    for (int i = 0; i < 8; i++) {
        int r = row0 + ty * 8 + i;
        if (r >= M) continue;
        float accf[8];
#pragma unroll
        for (int j = 0; j < 4; j++)
            UNPACK2(accf[2 * j], accf[2 * j + 1], acc2[i][j]);
#pragma unroll
        for (int j = 0; j < 8; j++) {
            int c = col0 + tx * 8 + j;
            if (c >= N) continue;
            float v = accf[j] + bias[c];
            if (MODE == MODE_DIST) {
                if (c < D) {
                    C[(size_t)r * ldc + c] = v;
                    C3[(size_t)r * D + c] = v;
                } else {
                    float sp = fmaxf(v, 0.0f) + log1pf(expf(-fabsf(v))) + 1e-7f;
                    C2[(size_t)r * ldc + (c - D)] = sp;
                }
            } else {
                C[(size_t)r * ldc + c] = v;
            }
        }
    }
}

// ---------------- host side ----------------

extern "C" void kernel_launch(void* const* d_in, const int* in_sizes, int n_in,
                              void* d_out, int out_size) {
    const float* atom_emb = (const float*)d_in[0];
    const float* edge_emb = (const float*)d_in[1];
    const float* eps      = (const float*)d_in[2];
    const float* conv_w1  = (const float*)d_in[3];
    const float* conv_b1  = (const float*)d_in[4];
    const float* bn1g     = (const float*)d_in[5];
    const float* bn1b     = (const float*)d_in[6];
    const float* conv_w2  = (const float*)d_in[7];
    const float* conv_b2  = (const float*)d_in[8];
    const float* bn_g     = (const float*)d_in[9];
    const float* bn_b     = (const float*)d_in[10];
    const float* dist_w   = (const float*)d_in[11];
    const float* dist_b   = (const float*)d_in[12];
    const float* dec_w1   = (const float*)d_in[13];
    const float* dec_b1   = (const float*)d_in[14];
    const float* dec_bng  = (const float*)d_in[15];
    const float* dec_bnb  = (const float*)d_in[16];
    const float* dec_w2   = (const float*)d_in[17];
    const float* dec_b2   = (const float*)d_in[18];
    const int* x_idx      = (const int*)d_in[19];
    const int* edge_attr  = (const int*)d_in[20];
    const int* edge_index = (const int*)d_in[21];
    const int* batch      = (const int*)d_in[22];
    float* out = (float*)d_out;

    void* sp = nullptr;
    cudaGetSymbolAddress(&sp, g_scratch);
    float* S = (float*)sp;
    float* h     = S + OFF_H;
    float* z     = S + OFF_Z;
    float* z1    = S + OFF_Z1;
    float* z2    = S + OFF_Z2;
    float* hg    = S + OFF_HG;
    float* mu    = S + OFF_MU;
    float* zdec  = S + OFF_ZDEC;
    float* stats = S + OFF_STATS;
    float* bnA   = S + OFF_BNA;
    float* bnB   = S + OFF_BNB;

    const int TB = 256;
    const int gNode = (NNODE * D4 + TB - 1) / TB;
    const int gEdge = (NEDGE * D4 + TB - 1) / TB;

    k_gather<<<gNode, TB>>>(atom_emb, x_idx, h);

    for (int l = 0; l < NLAYER; l++) {
        k_scale<<<gNode, TB>>>(h, eps, l, z);
        k_edge<<<gEdge, TB>>>(h, edge_emb + (size_t)l * 5 * D, edge_attr, edge_index, z);

        dim3 g1((HDIM + BN - 1) / BN, (NNODE + BM - 1) / BM);
        k_gemm<MODE_PLAIN, true><<<g1, 256>>>(z, conv_w1 + (size_t)l * D * HDIM,
                                        conv_b1 + (size_t)l * HDIM,
                                        z1, nullptr, nullptr,
                                        NNODE, HDIM, D, HDIM, HDIM, HDIM,
                                        nullptr, nullptr);
        k_zero<<<(2432 + TB - 1) / TB, TB>>>(stats, 2432);
        dim3 gr1((HDIM + TB - 1) / TB, (NNODE + RED_ROWS - 1) / RED_ROWS);
        k_colreduce<<<gr1, TB>>>(z1, NNODE, HDIM, stats);
        k_bnparam<<<(HDIM + TB - 1) / TB, TB>>>(stats, bn1g + (size_t)l * HDIM,
                                                bn1b + (size_t)l * HDIM,
                                                HDIM, 1.0f / NNODE, bnA, bnB);
        dim3 g2((D + BN - 1) / BN, (NNODE + BM - 1) / BM);
        k_gemm<MODE_BNRELU, true><<<g2, 256>>>(z1, conv_w2 + (size_t)l * HDIM * D,
                                         conv_b2 + (size_t)l * D,
                                         z2, nullptr, nullptr,
                                         NNODE, D, HDIM, D, D, D,
                                         bnA, bnB);
        k_zero<<<(2432 + TB - 1) / TB, TB>>>(stats, 2432);
        dim3 gr2((D + TB - 1) / TB, (NNODE + RED_ROWS - 1) / RED_ROWS);
        k_colreduce<<<gr2, TB>>>(z2, NNODE, D, stats);
        k_bnparam<<<(D + TB - 1) / TB, TB>>>(stats, bn_g + (size_t)l * D,
                                             bn_b + (size_t)l * D,
                                             D, 1.0f / NNODE, bnA, bnB);
        k_finalize<<<gNode, TB>>>(z2, bnA, bnB, (l < NLAYER - 1) ? 1 : 0, h);
    }

    k_hginit<<<(NGRAPH * D + TB - 1) / TB, TB>>>(hg);
    k_segmax<<<gNode, TB>>>(h, batch, hg);

    {
        dim3 gd((HDIM + BN - 1) / BN, (NGRAPH + BM - 1) / BM);
        k_gemm<MODE_DIST, true><<<gd, 256>>>(hg, dist_w, dist_b,
                                       out,
                                       out + (size_t)NGRAPH * D,
                                       mu,
                                       NGRAPH, HDIM, D, HDIM, HDIM, D,
                                       nullptr, nullptr);
    }

    const int ddims[6] = {1024, 1111, 862, 1783, 966, 978};
    const size_t dbase[6] = {
        2457600ull,
        6651904ull,
        6651904ull + 1111ull,
        14733312ull,
        14733312ull + 1783ull,
        25993216ull
    };
    const int dldc[6] = {1024, 1973, 1973, 2749, 2749, 978};

    for (int i = 0; i < 6; i++) {
        dim3 gd1((DECH + BN - 1) / BN, (NGRAPH + BM - 1) / BM);
        k_gemm<MODE_PLAIN, true><<<gd1, 256>>>(mu, dec_w1 + (size_t)i * D * DECH,
                                         dec_b1 + (size_t)i * DECH,
                                         zdec, nullptr, nullptr,
                                         NGRAPH, DECH, D, DECH, DECH, DECH,
                                         nullptr, nullptr);
        k_zero<<<(2432 + TB - 1) / TB, TB>>>(stats, 2432);
        dim3 grd((DECH + TB - 1) / TB, (NGRAPH + RED_ROWS - 1) / RED_ROWS);
        k_colreduce<<<grd, TB>>>(zdec, NGRAPH, DECH, stats);
        k_bnparam<<<(DECH + TB - 1) / TB, TB>>>(stats, dec_bng + (size_t)i * DECH,
                                                dec_bnb + (size_t)i * DECH,
                                                DECH, 1.0f / NGRAPH, bnA, bnB);
        dim3 gd2((ddims[i] + BN - 1) / BN, (NGRAPH + BM - 1) / BM);
        k_gemm<MODE_DEC, false><<<gd2, 256>>>(zdec, dec_w2 + (size_t)i * DECH * MAXO,
                                       dec_b2 + (size_t)i * MAXO,
                                       out + dbase[i], nullptr, nullptr,
                                       NGRAPH, ddims[i], DECH, MAXO, MAXO, dldc[i],
                                       bnA, bnB);
    }
}